// round 3
// baseline (speedup 1.0000x reference)
#include <cuda_runtime.h>

// Problem constants
#define BB   8
#define CC   512
#define HH   128
#define WW   128
#define DSF  4
#define HP   32          // HH/DSF
#define WP   32          // WW/DSF
#define NN   1024        // HP*WP
#define CKK  128         // CC/4

// Scratch (static device globals — allowed; no runtime allocation)
__device__ float g_xpool[BB * CC * NN];       // pooled input   [B,C,N]
__device__ float g_ypool[BB * CC * NN];       // pooled c2      [B,C,N]
__device__ float g_q[BB * CKK * NN];          // [B,Ck,N]
__device__ float g_k[BB * CKK * NN];          // [B,Ck,N]
__device__ float g_v[BB * CC * NN];           // [B,C,N]
__device__ float g_attn[BB * NN * NN];        // [B,N,N] energy -> softmax in place
__device__ float g_osm[BB * CC * NN];         // attention output small [B,C,N]

// ---------------------------------------------------------------------------
// Kernel 1: 4x4 average pooling of both input and c2.
// blockIdx.y selects tensor. One thread per pooled element; 4 float4 row loads.
// ---------------------------------------------------------------------------
__global__ __launch_bounds__(256) void pool_kernel(const float* __restrict__ in,
                                                   const float* __restrict__ c2) {
    int idx = blockIdx.x * 256 + threadIdx.x;          // over B*C*HP*WP
    if (idx >= BB * CC * NN) return;
    const float* __restrict__ src = blockIdx.y ? c2 : in;
    float* __restrict__ dst       = blockIdx.y ? g_ypool : g_xpool;

    int pw = idx & (WP - 1);
    int ph = (idx >> 5) & (HP - 1);
    int bc = idx >> 10;                                // b*C + c

    int base = (bc * HH + ph * DSF) * WW + pw * DSF;
    float s = 0.f;
#pragma unroll
    for (int r = 0; r < DSF; r++) {
        float4 vv = *reinterpret_cast<const float4*>(src + base + r * WW);
        s += vv.x + vv.y + vv.z + vv.w;
    }
    dst[idx] = s * (1.f / 16.f);
}

// ---------------------------------------------------------------------------
// Kernel 2: Out[b][m][n] = sum_k Wm[m][k] * X[b][k][n] + bias[m]
// K = CC = 512. Tile 64x64x32, 256 threads, 4x4 per thread.
// ---------------------------------------------------------------------------
__global__ __launch_bounds__(256) void gemm_wx_kernel(const float* __restrict__ Wm,
                                                      const float* __restrict__ bias,
                                                      const float* __restrict__ X,
                                                      float* __restrict__ Out, int O) {
    __shared__ float sA[32][65];   // [kk][mm]  (transposed on load)
    __shared__ float sB[32][64];   // [kk][nn]

    const int b  = blockIdx.z;
    const int m0 = blockIdx.y * 64;
    const int n0 = blockIdx.x * 64;
    const float* __restrict__ Xb = X + (size_t)b * CC * NN;

    const int t  = threadIdx.x;
    const int tx = t & 15;
    const int ty = t >> 4;

    float acc[4][4] = {};

    for (int k0 = 0; k0 < CC; k0 += 32) {
        {   // load W tile: coalesced over kk, shared-write stride 65 -> conflict-free
            int kk = t & 31, mb = t >> 5;
#pragma unroll
            for (int i = 0; i < 8; i++) {
                int mm = mb + i * 8;
                sA[kk][mm] = Wm[(m0 + mm) * CC + k0 + kk];
            }
        }
        {   // load X tile: coalesced over nn
            int nn = t & 63, kb = t >> 6;
#pragma unroll
            for (int i = 0; i < 8; i++) {
                int kk = kb + i * 4;
                sB[kk][nn] = Xb[(k0 + kk) * NN + n0 + nn];
            }
        }
        __syncthreads();
#pragma unroll
        for (int kk = 0; kk < 32; kk++) {
            float a[4], bb[4];
#pragma unroll
            for (int i = 0; i < 4; i++) a[i]  = sA[kk][ty + 16 * i];
#pragma unroll
            for (int j = 0; j < 4; j++) bb[j] = sB[kk][tx + 16 * j];
#pragma unroll
            for (int i = 0; i < 4; i++)
#pragma unroll
                for (int j = 0; j < 4; j++) acc[i][j] += a[i] * bb[j];
        }
        __syncthreads();
    }

    float* __restrict__ Ob = Out + (size_t)b * O * NN;
#pragma unroll
    for (int i = 0; i < 4; i++) {
        int m = m0 + ty + 16 * i;
        float bia = bias[m];
#pragma unroll
        for (int j = 0; j < 4; j++)
            Ob[m * NN + n0 + tx + 16 * j] = acc[i][j] + bia;
    }
}

// ---------------------------------------------------------------------------
// Kernel 3: energy[b][n][m] = scale * sum_o q[b][o][n] * k[b][o][m]
// Both operands are already [K=128][N] (o-major) -> direct coalesced tile loads.
// ---------------------------------------------------------------------------
__global__ __launch_bounds__(256) void energy_kernel(const float* __restrict__ q,
                                                     const float* __restrict__ k,
                                                     float* __restrict__ attn) {
    __shared__ float sQ[32][64];   // [kk][nn]
    __shared__ float sK[32][64];   // [kk][mm]

    const int b  = blockIdx.z;
    const int n0 = blockIdx.y * 64;
    const int m0 = blockIdx.x * 64;
    const float* __restrict__ qb = q + (size_t)b * CKK * NN;
    const float* __restrict__ kb = k + (size_t)b * CKK * NN;

    const int t  = threadIdx.x;
    const int tx = t & 15;
    const int ty = t >> 4;

    float acc[4][4] = {};

    for (int k0 = 0; k0 < CKK; k0 += 32) {
        int cl = t & 63, kbase = t >> 6;
#pragma unroll
        for (int i = 0; i < 8; i++) {
            int kk = kbase + i * 4;
            sQ[kk][cl] = qb[(k0 + kk) * NN + n0 + cl];
            sK[kk][cl] = kb[(k0 + kk) * NN + m0 + cl];
        }
        __syncthreads();
#pragma unroll
        for (int kk = 0; kk < 32; kk++) {
            float a[4], bb[4];
#pragma unroll
            for (int i = 0; i < 4; i++) a[i]  = sQ[kk][ty + 16 * i];
#pragma unroll
            for (int j = 0; j < 4; j++) bb[j] = sK[kk][tx + 16 * j];
#pragma unroll
            for (int i = 0; i < 4; i++)
#pragma unroll
                for (int j = 0; j < 4; j++) acc[i][j] += a[i] * bb[j];
        }
        __syncthreads();
    }

    const float scale = 0.088388347648318447f;  // 128^-0.5
    float* __restrict__ ab = attn + (size_t)b * NN * NN;
#pragma unroll
    for (int i = 0; i < 4; i++)
#pragma unroll
        for (int j = 0; j < 4; j++)
            ab[(size_t)(n0 + ty + 16 * i) * NN + m0 + tx + 16 * j] = acc[i][j] * scale;
}

// ---------------------------------------------------------------------------
// Kernel 4: row softmax over last dim (N=1024), in place. One block per row.
// ---------------------------------------------------------------------------
__global__ __launch_bounds__(256) void softmax_kernel(float* __restrict__ attn) {
    __shared__ float red[8];
    float* __restrict__ p = attn + (size_t)blockIdx.x * NN;
    const int t = threadIdx.x;

    float v[4];
    float mx = -3.4e38f;
#pragma unroll
    for (int i = 0; i < 4; i++) {
        v[i] = p[t + 256 * i];
        mx = fmaxf(mx, v[i]);
    }
#pragma unroll
    for (int o = 16; o > 0; o >>= 1) mx = fmaxf(mx, __shfl_xor_sync(0xffffffffu, mx, o));
    if ((t & 31) == 0) red[t >> 5] = mx;
    __syncthreads();
    if (t < 8) {
        float m = red[t];
#pragma unroll
        for (int o = 4; o > 0; o >>= 1) m = fmaxf(m, __shfl_xor_sync(0xffu, m, o));
        red[t] = m;
    }
    __syncthreads();
    mx = red[0];

    float s = 0.f;
#pragma unroll
    for (int i = 0; i < 4; i++) {
        v[i] = __expf(v[i] - mx);
        s += v[i];
    }
#pragma unroll
    for (int o = 16; o > 0; o >>= 1) s += __shfl_xor_sync(0xffffffffu, s, o);
    __syncthreads();
    if ((t & 31) == 0) red[t >> 5] = s;
    __syncthreads();
    if (t < 8) {
        float m = red[t];
#pragma unroll
        for (int o = 4; o > 0; o >>= 1) m += __shfl_xor_sync(0xffu, m, o);
        red[t] = m;
    }
    __syncthreads();
    float inv = 1.f / red[0];
#pragma unroll
    for (int i = 0; i < 4; i++) p[t + 256 * i] = v[i] * inv;
}

// ---------------------------------------------------------------------------
// Kernel 5: outS[b][c][n] = sum_m v[b][c][m] * attn[b][n][m]   (A @ B^T, K=1024)
// Both operands are m-major rows -> transpose on load into padded shared.
// ---------------------------------------------------------------------------
__global__ __launch_bounds__(256) void av_kernel(const float* __restrict__ vmat,
                                                 const float* __restrict__ attn,
                                                 float* __restrict__ outS) {
    __shared__ float sV[32][65];   // [kk][cc]
    __shared__ float sT[32][65];   // [kk][nn]

    const int b  = blockIdx.z;
    const int c0 = blockIdx.y * 64;
    const int n0 = blockIdx.x * 64;
    const float* __restrict__ vb = vmat + (size_t)b * CC * NN;
    const float* __restrict__ ab = attn + (size_t)b * NN * NN;

    const int t  = threadIdx.x;
    const int tx = t & 15;
    const int ty = t >> 4;

    float acc[4][4] = {};

    for (int k0 = 0; k0 < NN; k0 += 32) {
        int kk = t & 31, rb = t >> 5;
#pragma unroll
        for (int i = 0; i < 8; i++) {
            int r = rb + 8 * i;
            sV[kk][r] = vb[(c0 + r) * NN + k0 + kk];              // coalesced over kk
            sT[kk][r] = ab[(size_t)(n0 + r) * NN + k0 + kk];      // coalesced over kk
        }
        __syncthreads();
#pragma unroll
        for (int kq = 0; kq < 32; kq++) {
            float a[4], bb[4];
#pragma unroll
            for (int i = 0; i < 4; i++) a[i]  = sV[kq][ty + 16 * i];
#pragma unroll
            for (int j = 0; j < 4; j++) bb[j] = sT[kq][tx + 16 * j];
#pragma unroll
            for (int i = 0; i < 4; i++)
#pragma unroll
                for (int j = 0; j < 4; j++) acc[i][j] += a[i] * bb[j];
        }
        __syncthreads();
    }

    float* __restrict__ ob = outS + (size_t)b * CC * NN;
#pragma unroll
    for (int i = 0; i < 4; i++)
#pragma unroll
        for (int j = 0; j < 4; j++)
            ob[(c0 + ty + 16 * i) * NN + n0 + tx + 16 * j] = acc[i][j];
}

// ---------------------------------------------------------------------------
// Kernel 6: out[b,c,y,x] = outS[b,c,y/4,x/4] + c2[b,c,y,x]   (nearest upsample + add)
// One thread per 4 consecutive x (all map to the same small pixel).
// ---------------------------------------------------------------------------
__global__ __launch_bounds__(256) void up_add_kernel(const float* __restrict__ c2,
                                                     float* __restrict__ out) {
    int idx = blockIdx.x * 256 + threadIdx.x;           // over B*C*H*(W/4)
    if (idx >= BB * CC * HH * (WW / 4)) return;
    int xq = idx & 31;                                  // W/4 = 32
    int y  = (idx >> 5) & (HH - 1);
    int bc = idx >> 12;

    float add = g_osm[(size_t)bc * NN + (y >> 2) * WP + xq];
    size_t off = ((size_t)bc * HH + y) * WW + xq * 4;
    float4 c = *reinterpret_cast<const float4*>(c2 + off);
    c.x += add; c.y += add; c.z += add; c.w += add;
    *reinterpret_cast<float4*>(out + off) = c;
}

// ---------------------------------------------------------------------------
extern "C" void kernel_launch(void* const* d_in, const int* in_sizes, int n_in,
                              void* d_out, int out_size) {
    const float* input = (const float*)d_in[0];
    const float* c2    = (const float*)d_in[1];
    const float* Wq    = (const float*)d_in[2];
    const float* bq    = (const float*)d_in[3];
    const float* Wk    = (const float*)d_in[4];
    const float* bk    = (const float*)d_in[5];
    const float* Wv    = (const float*)d_in[6];
    const float* bv    = (const float*)d_in[7];
    float* out = (float*)d_out;

    float *xp, *yp, *q, *k, *v, *attn, *osm;
    cudaGetSymbolAddress((void**)&xp,   g_xpool);
    cudaGetSymbolAddress((void**)&yp,   g_ypool);
    cudaGetSymbolAddress((void**)&q,    g_q);
    cudaGetSymbolAddress((void**)&k,    g_k);
    cudaGetSymbolAddress((void**)&v,    g_v);
    cudaGetSymbolAddress((void**)&attn, g_attn);
    cudaGetSymbolAddress((void**)&osm,  g_osm);

    // 1. pooling (both tensors)
    {
        dim3 grid((BB * CC * NN + 255) / 256, 2);
        pool_kernel<<<grid, 256>>>(input, c2);
    }
    // 2. q, k, v projections
    gemm_wx_kernel<<<dim3(NN / 64, CKK / 64, BB), 256>>>(Wq, bq, xp, q, CKK);
    gemm_wx_kernel<<<dim3(NN / 64, CKK / 64, BB), 256>>>(Wk, bk, yp, k, CKK);
    gemm_wx_kernel<<<dim3(NN / 64, CC  / 64, BB), 256>>>(Wv, bv, yp, v, CC);
    // 3. energy = scale * q^T k
    energy_kernel<<<dim3(NN / 64, NN / 64, BB), 256>>>(q, k, attn);
    // 4. softmax rows
    softmax_kernel<<<BB * NN, 256>>>(attn);
    // 5. outS = v @ attn^T
    av_kernel<<<dim3(NN / 64, CC / 64, BB), 256>>>(v, attn, osm);
    // 6. upsample + residual add
    up_add_kernel<<<(BB * CC * HH * (WW / 4) + 255) / 256, 256>>>(c2, out);
}

// round 4
// speedup vs baseline: 3.6953x; 3.6953x over previous
#include <cuda_runtime.h>
#include <cuda_bf16.h>
#include <stdint.h>

#define BB   8
#define CC   512
#define HH   128
#define WW   128
#define HP   32
#define WP   32
#define NN   1024        // HP*WP tokens
#define CKK  128         // C/4

typedef __nv_bfloat16 bf16;

// ------------------------- scratch (static device globals) -------------------
__device__ bf16  g_xT[(size_t)BB * NN * CC];     // pooled input, [b][n][c]
__device__ bf16  g_yT[(size_t)BB * NN * CC];     // pooled c2,    [b][n][c]
__device__ bf16  g_Wqb[CKK * CC];
__device__ bf16  g_Wkb[CKK * CC];
__device__ bf16  g_Wvb[CC * CC];
__device__ bf16  g_Q [(size_t)BB * NN * CKK];    // [b][n][o]
__device__ bf16  g_Kt[(size_t)BB * NN * CKK];    // [b][m][o]
__device__ bf16  g_V [(size_t)BB * CC * NN];     // [b][c][n]
__device__ float g_E [(size_t)BB * NN * NN];     // [b][n][m]
__device__ bf16  g_attn[(size_t)BB * NN * NN];   // [b][n][m] softmaxed
__device__ float g_osm[(size_t)BB * CC * NN];    // [b][c][n] attention out

// ---------------------------------------------------------------------------
// Kernel 1: fused 4x4 avg-pool + transpose + bf16 convert (both tensors).
// Block: 1024 threads = 32 channels x 32 pooled-w, one pooled row (ph) each.
// ---------------------------------------------------------------------------
__global__ __launch_bounds__(1024) void pool_t_kernel(const float* __restrict__ in,
                                                      const float* __restrict__ c2) {
    const int cg = blockIdx.x;            // channel group of 32
    const int ph = blockIdx.y;            // pooled row
    const int b  = blockIdx.z >> 1;
    const float* __restrict__ src = (blockIdx.z & 1) ? c2 : in;
    bf16* __restrict__ dst            = (blockIdx.z & 1) ? g_yT : g_xT;

    const int t  = threadIdx.x;
    const int cl = t >> 5;                // 0..31 channel-local
    const int pw = t & 31;                // 0..31 pooled col

    const size_t base = ((size_t)(b * CC + cg * 32 + cl) * HH + ph * 4) * WW + pw * 4;
    float s = 0.f;
#pragma unroll
    for (int r = 0; r < 4; r++) {
        float4 v = *reinterpret_cast<const float4*>(src + base + r * WW);
        s += v.x + v.y + v.z + v.w;
    }

    __shared__ bf16 tile[32][33];         // [pw][cl]
    tile[pw][cl] = __float2bfloat16(s * (1.f / 16.f));
    __syncthreads();

    // remapped write: warp = one token row n, 32 contiguous channels
    const int pwo = t >> 5, clo = t & 31;
    dst[((size_t)b * NN + ph * 32 + pwo) * CC + cg * 32 + clo] = tile[pwo][clo];
}

// ---------------------------------------------------------------------------
// Kernel 2: fp32 -> bf16 weight conversion
// ---------------------------------------------------------------------------
__global__ __launch_bounds__(256) void cvt_w_kernel(const float* __restrict__ Wq,
                                                    const float* __restrict__ Wk,
                                                    const float* __restrict__ Wv) {
    int i = blockIdx.x * 256 + threadIdx.x;
    if (i < CKK * CC) {
        g_Wqb[i] = __float2bfloat16(Wq[i]);
        g_Wkb[i] = __float2bfloat16(Wk[i]);
    }
    if (i < CC * CC) g_Wvb[i] = __float2bfloat16(Wv[i]);
}

// ---------------------------------------------------------------------------
// Kernel 3: batched TN bf16 GEMM via mma.sync.m16n8k16 (fp32 accumulate)
//   C[m][n] = sum_k A[m][k] * B[n][k]  (+bias)
// Block tile 128x128, BK=32, 8 warps (2x4), warp tile 64x32.
// BIAS_MODE: 0 none, 1 per-row(m), 2 per-col(n).  OUT_BF16 selects C dtype.
// All dims are exact multiples (M%128==0, N%128==0, K%32==0) -> no guards.
// ---------------------------------------------------------------------------
#define SAS 40   // smem row stride in bf16 (conflict-free for frag loads)

__device__ __forceinline__ void mma_bf16(float* c, const uint32_t* a, const uint32_t* b) {
    asm volatile(
        "mma.sync.aligned.m16n8k16.row.col.f32.bf16.bf16.f32 "
        "{%0,%1,%2,%3}, {%4,%5,%6,%7}, {%8,%9}, {%0,%1,%2,%3};"
        : "+f"(c[0]), "+f"(c[1]), "+f"(c[2]), "+f"(c[3])
        : "r"(a[0]), "r"(a[1]), "r"(a[2]), "r"(a[3]), "r"(b[0]), "r"(b[1]));
}

template <int BIAS_MODE, bool OUT_BF16>
__global__ __launch_bounds__(256, 2) void mma_tn_kernel(
    const bf16* __restrict__ A, const bf16* __restrict__ B,
    const float* __restrict__ bias, void* __restrict__ Cout,
    int Kk, int lda, int ldb, int ldc,
    size_t strideA, size_t strideB, size_t strideC) {

    __shared__ bf16 sA[128][SAS];
    __shared__ bf16 sB[128][SAS];

    const int m0 = blockIdx.y * 128;
    const int n0 = blockIdx.x * 128;
    const bf16* __restrict__ Ab = A + strideA * blockIdx.z;
    const bf16* __restrict__ Bb = B + strideB * blockIdx.z;

    const int t    = threadIdx.x;
    const int warp = t >> 5;
    const int lane = t & 31;
    const int wm   = (warp >> 2) * 64;    // warp m offset (0 or 64)
    const int wn   = (warp & 3) * 32;     // warp n offset
    const int g    = lane >> 2;           // group id 0..7
    const int tg   = lane & 3;            // thread-in-group

    float acc[4][4][4];
#pragma unroll
    for (int i = 0; i < 4; i++)
#pragma unroll
        for (int j = 0; j < 4; j++)
#pragma unroll
            for (int e = 0; e < 4; e++) acc[i][j][e] = 0.f;

    for (int k0 = 0; k0 < Kk; k0 += 32) {
        // stage 128x32 bf16 tiles of A and B (16B chunks, coalesced)
#pragma unroll
        for (int i = 0; i < 2; i++) {
            int ch = t + 256 * i;
            int r  = ch >> 2;
            int o  = (ch & 3) * 8;
            *reinterpret_cast<uint4*>(&sA[r][o]) =
                *reinterpret_cast<const uint4*>(&Ab[(size_t)(m0 + r) * lda + k0 + o]);
            *reinterpret_cast<uint4*>(&sB[r][o]) =
                *reinterpret_cast<const uint4*>(&Bb[(size_t)(n0 + r) * ldb + k0 + o]);
        }
        __syncthreads();

#pragma unroll
        for (int ks = 0; ks < 32; ks += 16) {
            uint32_t afr[4][4], bfr[4][2];
#pragma unroll
            for (int mi = 0; mi < 4; mi++) {
                int row = wm + mi * 16 + g;
                afr[mi][0] = *reinterpret_cast<const uint32_t*>(&sA[row][ks + 2 * tg]);
                afr[mi][1] = *reinterpret_cast<const uint32_t*>(&sA[row + 8][ks + 2 * tg]);
                afr[mi][2] = *reinterpret_cast<const uint32_t*>(&sA[row][ks + 2 * tg + 8]);
                afr[mi][3] = *reinterpret_cast<const uint32_t*>(&sA[row + 8][ks + 2 * tg + 8]);
            }
#pragma unroll
            for (int nj = 0; nj < 4; nj++) {
                int col = wn + nj * 8 + g;
                bfr[nj][0] = *reinterpret_cast<const uint32_t*>(&sB[col][ks + 2 * tg]);
                bfr[nj][1] = *reinterpret_cast<const uint32_t*>(&sB[col][ks + 2 * tg + 8]);
            }
#pragma unroll
            for (int mi = 0; mi < 4; mi++)
#pragma unroll
                for (int nj = 0; nj < 4; nj++)
                    mma_bf16(acc[mi][nj], afr[mi], bfr[nj]);
        }
        __syncthreads();
    }

    // epilogue
#pragma unroll
    for (int mi = 0; mi < 4; mi++) {
#pragma unroll
        for (int nj = 0; nj < 4; nj++) {
            int row = m0 + wm + mi * 16 + g;
            int col = n0 + wn + nj * 8 + 2 * tg;
            float c0 = acc[mi][nj][0], c1 = acc[mi][nj][1];
            float c2v = acc[mi][nj][2], c3v = acc[mi][nj][3];
            if (BIAS_MODE == 1) {
                float br0 = bias[row], br1 = bias[row + 8];
                c0 += br0; c1 += br0; c2v += br1; c3v += br1;
            } else if (BIAS_MODE == 2) {
                float bc0 = bias[col], bc1 = bias[col + 1];
                c0 += bc0; c1 += bc1; c2v += bc0; c3v += bc1;
            }
            if (OUT_BF16) {
                bf16* Cb = reinterpret_cast<bf16*>(Cout) + strideC * blockIdx.z;
                __nv_bfloat162 p0 = __floats2bfloat162_rn(c0, c1);
                __nv_bfloat162 p1 = __floats2bfloat162_rn(c2v, c3v);
                *reinterpret_cast<__nv_bfloat162*>(&Cb[(size_t)row * ldc + col]) = p0;
                *reinterpret_cast<__nv_bfloat162*>(&Cb[(size_t)(row + 8) * ldc + col]) = p1;
            } else {
                float* Cf = reinterpret_cast<float*>(Cout) + strideC * blockIdx.z;
                *reinterpret_cast<float2*>(&Cf[(size_t)row * ldc + col]) = make_float2(c0, c1);
                *reinterpret_cast<float2*>(&Cf[(size_t)(row + 8) * ldc + col]) = make_float2(c2v, c3v);
            }
        }
    }
}

// ---------------------------------------------------------------------------
// Kernel 4: row softmax of scale*E (N=1024), fp32 in -> bf16 out.
// ---------------------------------------------------------------------------
__global__ __launch_bounds__(256) void softmax_kernel() {
    __shared__ float red[8];
    const float* __restrict__ p = g_E + (size_t)blockIdx.x * NN;
    bf16* __restrict__ po       = g_attn + (size_t)blockIdx.x * NN;
    const int t = threadIdx.x;
    const float scale = 0.088388347648318447f;   // 128^-0.5

    float v[4];
    float mx = -3.4e38f;
#pragma unroll
    for (int i = 0; i < 4; i++) {
        v[i] = p[t + 256 * i] * scale;
        mx = fmaxf(mx, v[i]);
    }
#pragma unroll
    for (int o = 16; o > 0; o >>= 1) mx = fmaxf(mx, __shfl_xor_sync(0xffffffffu, mx, o));
    if ((t & 31) == 0) red[t >> 5] = mx;
    __syncthreads();
    if (t < 8) {
        float m = red[t];
#pragma unroll
        for (int o = 4; o > 0; o >>= 1) m = fmaxf(m, __shfl_xor_sync(0xffu, m, o));
        red[t] = m;
    }
    __syncthreads();
    mx = red[0];

    float s = 0.f;
#pragma unroll
    for (int i = 0; i < 4; i++) {
        v[i] = __expf(v[i] - mx);
        s += v[i];
    }
#pragma unroll
    for (int o = 16; o > 0; o >>= 1) s += __shfl_xor_sync(0xffffffffu, s, o);
    __syncthreads();
    if ((t & 31) == 0) red[t >> 5] = s;
    __syncthreads();
    if (t < 8) {
        float m = red[t];
#pragma unroll
        for (int o = 4; o > 0; o >>= 1) m += __shfl_xor_sync(0xffu, m, o);
        red[t] = m;
    }
    __syncthreads();
    float inv = 1.f / red[0];
#pragma unroll
    for (int i = 0; i < 4; i++) po[t + 256 * i] = __float2bfloat16(v[i] * inv);
}

// ---------------------------------------------------------------------------
// Kernel 5: nearest upsample 4x + residual add.
// ---------------------------------------------------------------------------
__global__ __launch_bounds__(256) void up_add_kernel(const float* __restrict__ c2,
                                                     float* __restrict__ out) {
    int idx = blockIdx.x * 256 + threadIdx.x;           // over B*C*H*(W/4)
    if (idx >= BB * CC * HH * (WW / 4)) return;
    int xq = idx & 31;
    int y  = (idx >> 5) & (HH - 1);
    int bc = idx >> 12;

    float add = g_osm[(size_t)bc * NN + (y >> 2) * WP + xq];
    size_t off = ((size_t)bc * HH + y) * WW + xq * 4;
    float4 c = *reinterpret_cast<const float4*>(c2 + off);
    c.x += add; c.y += add; c.z += add; c.w += add;
    *reinterpret_cast<float4*>(out + off) = c;
}

// ---------------------------------------------------------------------------
extern "C" void kernel_launch(void* const* d_in, const int* in_sizes, int n_in,
                              void* d_out, int out_size) {
    const float* input = (const float*)d_in[0];
    const float* c2    = (const float*)d_in[1];
    const float* Wq    = (const float*)d_in[2];
    const float* bq    = (const float*)d_in[3];
    const float* Wk    = (const float*)d_in[4];
    const float* bk    = (const float*)d_in[5];
    const float* Wv    = (const float*)d_in[6];
    const float* bv    = (const float*)d_in[7];
    float* out = (float*)d_out;

    bf16 *xT, *yT, *wqb, *wkb, *wvb, *Qp, *Kp, *Vp, *attn;
    float *Ep, *osm;
    cudaGetSymbolAddress((void**)&xT,   g_xT);
    cudaGetSymbolAddress((void**)&yT,   g_yT);
    cudaGetSymbolAddress((void**)&wqb,  g_Wqb);
    cudaGetSymbolAddress((void**)&wkb,  g_Wkb);
    cudaGetSymbolAddress((void**)&wvb,  g_Wvb);
    cudaGetSymbolAddress((void**)&Qp,   g_Q);
    cudaGetSymbolAddress((void**)&Kp,   g_Kt);
    cudaGetSymbolAddress((void**)&Vp,   g_V);
    cudaGetSymbolAddress((void**)&Ep,   g_E);
    cudaGetSymbolAddress((void**)&attn, g_attn);
    cudaGetSymbolAddress((void**)&osm,  g_osm);

    // 1. pool + transpose + bf16 (both tensors);  2. weight conversion
    pool_t_kernel<<<dim3(CC / 32, HP, BB * 2), 1024>>>(input, c2);
    cvt_w_kernel<<<(CC * CC + 255) / 256, 256>>>(Wq, Wk, Wv);

    // 3. Q[n][o] = xT . Wq^T + bq   (M=1024, N=128, K=512), bf16 out
    mma_tn_kernel<2, true><<<dim3(1, 8, BB), 256>>>(
        xT, wqb, bq, Qp, CC, CC, CC, CKK,
        (size_t)NN * CC, 0, (size_t)NN * CKK);
    //    K[m][o] = yT . Wk^T + bk
    mma_tn_kernel<2, true><<<dim3(1, 8, BB), 256>>>(
        yT, wkb, bk, Kp, CC, CC, CC, CKK,
        (size_t)NN * CC, 0, (size_t)NN * CKK);
    //    V[c][n] = Wv . yT^T + bv   (M=512, N=1024, K=512), bf16 out
    mma_tn_kernel<1, true><<<dim3(8, 4, BB), 256>>>(
        wvb, yT, bv, Vp, CC, CC, CC, NN,
        0, (size_t)NN * CC, (size_t)CC * NN);

    // 4. E[n][m] = Q . K^T          (M=1024, N=1024, K=128), fp32 out
    mma_tn_kernel<0, false><<<dim3(8, 8, BB), 256>>>(
        Qp, Kp, nullptr, Ep, CKK, CKK, CKK, NN,
        (size_t)NN * CKK, (size_t)NN * CKK, (size_t)NN * NN);

    // 5. softmax rows (scale folded in), bf16 attn out
    softmax_kernel<<<BB * NN, 256>>>();

    // 6. osm[c][n] = V . attn^T     (M=512, N=1024, K=1024), fp32 out
    mma_tn_kernel<0, false><<<dim3(8, 4, BB), 256>>>(
        Vp, attn, nullptr, osm, NN, NN, NN, NN,
        (size_t)CC * NN, (size_t)NN * NN, (size_t)CC * NN);

    // 7. upsample + residual
    up_add_kernel<<<(BB * CC * HH * (WW / 4) + 255) / 256, 256>>>(c2, out);
}

// round 5
// speedup vs baseline: 4.3298x; 1.1717x over previous
#include <cuda_runtime.h>
#include <cuda_bf16.h>
#include <stdint.h>

#define BB   8
#define CC   512
#define HH   128
#define WW   128
#define HP   32
#define WP   32
#define NN   1024        // HP*WP tokens
#define CKK  128         // C/4

typedef __nv_bfloat16 bf16;

// ------------------------- scratch (static device globals) -------------------
__device__ bf16  g_xT[(size_t)BB * NN * CC];     // pooled input, [b][n][c]
__device__ bf16  g_yT[(size_t)BB * NN * CC];     // pooled c2,    [b][n][c]
__device__ bf16  g_Wqb[CKK * CC];
__device__ bf16  g_Wkb[CKK * CC];
__device__ bf16  g_Wvb[CC * CC];
__device__ bf16  g_Q [(size_t)BB * NN * CKK];    // [b][n][o]
__device__ bf16  g_Kt[(size_t)BB * NN * CKK];    // [b][m][o]
__device__ bf16  g_V [(size_t)BB * CC * NN];     // [b][c][n]
__device__ float g_E [(size_t)BB * NN * NN];     // [b][n][m]
__device__ bf16  g_attn[(size_t)BB * NN * NN];   // [b][n][m] softmaxed
__device__ float g_osm[(size_t)BB * CC * NN];    // [b][c][n] attention out

// ---------------------------------------------------------------------------
// Kernel 1: fused 4x4 avg-pool + transpose + bf16 convert (both tensors).
// ---------------------------------------------------------------------------
__global__ __launch_bounds__(1024) void pool_t_kernel(const float* __restrict__ in,
                                                      const float* __restrict__ c2) {
    const int cg = blockIdx.x;
    const int ph = blockIdx.y;
    const int b  = blockIdx.z >> 1;
    const float* __restrict__ src = (blockIdx.z & 1) ? c2 : in;
    bf16* __restrict__ dst            = (blockIdx.z & 1) ? g_yT : g_xT;

    const int t  = threadIdx.x;
    const int cl = t >> 5;
    const int pw = t & 31;

    const size_t base = ((size_t)(b * CC + cg * 32 + cl) * HH + ph * 4) * WW + pw * 4;
    float s = 0.f;
#pragma unroll
    for (int r = 0; r < 4; r++) {
        float4 v = *reinterpret_cast<const float4*>(src + base + r * WW);
        s += v.x + v.y + v.z + v.w;
    }

    __shared__ bf16 tile[32][33];
    tile[pw][cl] = __float2bfloat16(s * (1.f / 16.f));
    __syncthreads();

    const int pwo = t >> 5, clo = t & 31;
    dst[((size_t)b * NN + ph * 32 + pwo) * CC + cg * 32 + clo] = tile[pwo][clo];
}

// ---------------------------------------------------------------------------
// Kernel 2: fp32 -> bf16 weight conversion
// ---------------------------------------------------------------------------
__global__ __launch_bounds__(256) void cvt_w_kernel(const float* __restrict__ Wq,
                                                    const float* __restrict__ Wk,
                                                    const float* __restrict__ Wv) {
    int i = blockIdx.x * 256 + threadIdx.x;
    if (i < CKK * CC) {
        g_Wqb[i] = __float2bfloat16(Wq[i]);
        g_Wkb[i] = __float2bfloat16(Wk[i]);
    }
    if (i < CC * CC) g_Wvb[i] = __float2bfloat16(Wv[i]);
}

// ---------------------------------------------------------------------------
// PTX helpers
// ---------------------------------------------------------------------------
__device__ __forceinline__ void mma_bf16(float* c, const uint32_t* a, const uint32_t* b) {
    asm volatile(
        "mma.sync.aligned.m16n8k16.row.col.f32.bf16.bf16.f32 "
        "{%0,%1,%2,%3}, {%4,%5,%6,%7}, {%8,%9}, {%0,%1,%2,%3};"
        : "+f"(c[0]), "+f"(c[1]), "+f"(c[2]), "+f"(c[3])
        : "r"(a[0]), "r"(a[1]), "r"(a[2]), "r"(a[3]), "r"(b[0]), "r"(b[1]));
}

__device__ __forceinline__ void cp16(uint32_t saddr, const void* gptr) {
    asm volatile("cp.async.cg.shared.global [%0], [%1], 16;" :: "r"(saddr), "l"(gptr));
}
__device__ __forceinline__ void cp_commit() { asm volatile("cp.async.commit_group;"); }
__device__ __forceinline__ void cp_wait0()  { asm volatile("cp.async.wait_group 0;"); }

__device__ __forceinline__ void ldsm_x4(uint32_t* r, uint32_t saddr) {
    asm volatile("ldmatrix.sync.aligned.m8n8.x4.shared.b16 {%0,%1,%2,%3}, [%4];"
        : "=r"(r[0]), "=r"(r[1]), "=r"(r[2]), "=r"(r[3]) : "r"(saddr));
}

// ---------------------------------------------------------------------------
// Kernel 3: batched TN bf16 GEMM, 2-stage cp.async pipeline + ldmatrix.
//   C[m][n] = sum_k A[m][k] * B[n][k]  (+bias)
// Block tile 128x128, BK=32, 8 warps (2x4), warp tile 64x32.
// BIAS_MODE: 0 none, 1 per-row(m), 2 per-col(n).  OUT_BF16 selects C dtype.
// PAIR: grid.z = 2*zmod; z >= zmod switches to the second (A2,B2,bias2,C2) set.
// All dims are exact multiples (M%128==0, N%128==0, K%32==0) -> no guards.
// ---------------------------------------------------------------------------
#define SAS 40   // smem row stride in bf16: 80B -> ldmatrix rows hit 8 distinct 16B groups

template <int BIAS_MODE, bool OUT_BF16, bool PAIR>
__global__ __launch_bounds__(256, 2) void mma_tn_kernel(
    const bf16* __restrict__ A, const bf16* __restrict__ B,
    const float* __restrict__ bias, void* __restrict__ Cout,
    const bf16* __restrict__ A2, const bf16* __restrict__ B2,
    const float* __restrict__ bias2, void* __restrict__ Cout2,
    int Kk, int lda, int ldb, int ldc,
    size_t strideA, size_t strideB, size_t strideC, int zmod) {

    __shared__ bf16 sA[2][128][SAS];
    __shared__ bf16 sB[2][128][SAS];

    int bz = blockIdx.z;
    if (PAIR && bz >= zmod) {
        bz -= zmod;
        A = A2; B = B2; bias = bias2; Cout = Cout2;
    }

    const int m0 = blockIdx.y * 128;
    const int n0 = blockIdx.x * 128;
    const bf16* __restrict__ Ab = A + strideA * bz;
    const bf16* __restrict__ Bb = B + strideB * bz;

    const int t    = threadIdx.x;
    const int warp = t >> 5;
    const int lane = t & 31;
    const int wm   = (warp >> 2) * 64;
    const int wn   = (warp & 3) * 32;
    const int g    = lane >> 2;
    const int tg   = lane & 3;

    // cp.async staging coords: 2 chunks/thread/operand, 16B each
    const int ldr = t >> 2;               // 0..63 base row
    const int ldo = (t & 3) * 8;          // k offset in elements

    const uint32_t sAbase = (uint32_t)__cvta_generic_to_shared(&sA[0][0][0]);
    const uint32_t sBbase = (uint32_t)__cvta_generic_to_shared(&sB[0][0][0]);
    const uint32_t stageB = 128 * SAS * 2;          // bytes per stage

    // ldmatrix per-lane offsets
    const int aRow = (lane & 7) + ((lane >> 3) & 1) * 8;   // within 16-row tile
    const int aKof = (lane >> 4) * 8;
    const int bRow = (lane & 7) + ((lane >> 4) & 1) * 8;   // within 16-col group
    const int bKof = ((lane >> 3) & 1) * 8;

    float acc[4][4][4];
#pragma unroll
    for (int i = 0; i < 4; i++)
#pragma unroll
        for (int j = 0; j < 4; j++)
#pragma unroll
            for (int e = 0; e < 4; e++) acc[i][j][e] = 0.f;

    const int KT = Kk >> 5;   // number of 32-wide k tiles

    auto load_tile = [&](int kt, int s) {
        uint32_t sa = sAbase + s * stageB;
        uint32_t sb = sBbase + s * stageB;
        int k0 = kt * 32;
#pragma unroll
        for (int i = 0; i < 2; i++) {
            int r = ldr + 64 * i;
            cp16(sa + (r * SAS + ldo) * 2, &Ab[(size_t)(m0 + r) * lda + k0 + ldo]);
            cp16(sb + (r * SAS + ldo) * 2, &Bb[(size_t)(n0 + r) * ldb + k0 + ldo]);
        }
    };

    load_tile(0, 0);
    cp_commit();

    int buf = 0;
    for (int kt = 0; kt < KT; kt++) {
        cp_wait0();
        __syncthreads();                 // tile `buf` ready; prior compute on buf^1 done
        if (kt + 1 < KT) {
            load_tile(kt + 1, buf ^ 1);
            cp_commit();
        }

        uint32_t saS = sAbase + buf * stageB;
        uint32_t sbS = sBbase + buf * stageB;
#pragma unroll
        for (int ks = 0; ks < 32; ks += 16) {
            uint32_t afr[4][4];
#pragma unroll
            for (int mi = 0; mi < 4; mi++) {
                int row = wm + mi * 16 + aRow;
                ldsm_x4(afr[mi], saS + (row * SAS + ks + aKof) * 2);
            }
            uint32_t bfr[4][2];
#pragma unroll
            for (int nj2 = 0; nj2 < 2; nj2++) {
                uint32_t btmp[4];
                int col = wn + nj2 * 16 + bRow;
                ldsm_x4(btmp, sbS + (col * SAS + ks + bKof) * 2);
                bfr[nj2 * 2][0]     = btmp[0];
                bfr[nj2 * 2][1]     = btmp[1];
                bfr[nj2 * 2 + 1][0] = btmp[2];
                bfr[nj2 * 2 + 1][1] = btmp[3];
            }
#pragma unroll
            for (int mi = 0; mi < 4; mi++)
#pragma unroll
                for (int nj = 0; nj < 4; nj++)
                    mma_bf16(acc[mi][nj], afr[mi], bfr[nj]);
        }
        buf ^= 1;
    }

    // epilogue
#pragma unroll
    for (int mi = 0; mi < 4; mi++) {
#pragma unroll
        for (int nj = 0; nj < 4; nj++) {
            int row = m0 + wm + mi * 16 + g;
            int col = n0 + wn + nj * 8 + 2 * tg;
            float c0 = acc[mi][nj][0], c1 = acc[mi][nj][1];
            float c2v = acc[mi][nj][2], c3v = acc[mi][nj][3];
            if (BIAS_MODE == 1) {
                float br0 = bias[row], br1 = bias[row + 8];
                c0 += br0; c1 += br0; c2v += br1; c3v += br1;
            } else if (BIAS_MODE == 2) {
                float bc0 = bias[col], bc1 = bias[col + 1];
                c0 += bc0; c1 += bc1; c2v += bc0; c3v += bc1;
            }
            if (OUT_BF16) {
                bf16* Cb = reinterpret_cast<bf16*>(Cout) + strideC * bz;
                __nv_bfloat162 p0 = __floats2bfloat162_rn(c0, c1);
                __nv_bfloat162 p1 = __floats2bfloat162_rn(c2v, c3v);
                *reinterpret_cast<__nv_bfloat162*>(&Cb[(size_t)row * ldc + col]) = p0;
                *reinterpret_cast<__nv_bfloat162*>(&Cb[(size_t)(row + 8) * ldc + col]) = p1;
            } else {
                float* Cf = reinterpret_cast<float*>(Cout) + strideC * bz;
                *reinterpret_cast<float2*>(&Cf[(size_t)row * ldc + col]) = make_float2(c0, c1);
                *reinterpret_cast<float2*>(&Cf[(size_t)(row + 8) * ldc + col]) = make_float2(c2v, c3v);
            }
        }
    }
}

// ---------------------------------------------------------------------------
// Kernel 4: row softmax of scale*E (N=1024), fp32 in -> bf16 out.
// ---------------------------------------------------------------------------
__global__ __launch_bounds__(256) void softmax_kernel() {
    __shared__ float red[8];
    const float* __restrict__ p = g_E + (size_t)blockIdx.x * NN;
    bf16* __restrict__ po       = g_attn + (size_t)blockIdx.x * NN;
    const int t = threadIdx.x;
    const float scale = 0.088388347648318447f;   // 128^-0.5

    float v[4];
    float mx = -3.4e38f;
#pragma unroll
    for (int i = 0; i < 4; i++) {
        v[i] = p[t + 256 * i] * scale;
        mx = fmaxf(mx, v[i]);
    }
#pragma unroll
    for (int o = 16; o > 0; o >>= 1) mx = fmaxf(mx, __shfl_xor_sync(0xffffffffu, mx, o));
    if ((t & 31) == 0) red[t >> 5] = mx;
    __syncthreads();
    if (t < 8) {
        float m = red[t];
#pragma unroll
        for (int o = 4; o > 0; o >>= 1) m = fmaxf(m, __shfl_xor_sync(0xffu, m, o));
        red[t] = m;
    }
    __syncthreads();
    mx = red[0];

    float s = 0.f;
#pragma unroll
    for (int i = 0; i < 4; i++) {
        v[i] = __expf(v[i] - mx);
        s += v[i];
    }
#pragma unroll
    for (int o = 16; o > 0; o >>= 1) s += __shfl_xor_sync(0xffffffffu, s, o);
    __syncthreads();
    if ((t & 31) == 0) red[t >> 5] = s;
    __syncthreads();
    if (t < 8) {
        float m = red[t];
#pragma unroll
        for (int o = 4; o > 0; o >>= 1) m += __shfl_xor_sync(0xffu, m, o);
        red[t] = m;
    }
    __syncthreads();
    float inv = 1.f / red[0];
#pragma unroll
    for (int i = 0; i < 4; i++) po[t + 256 * i] = __float2bfloat16(v[i] * inv);
}

// ---------------------------------------------------------------------------
// Kernel 5: nearest upsample 4x + residual add.
// ---------------------------------------------------------------------------
__global__ __launch_bounds__(256) void up_add_kernel(const float* __restrict__ c2,
                                                     float* __restrict__ out) {
    int idx = blockIdx.x * 256 + threadIdx.x;
    if (idx >= BB * CC * HH * (WW / 4)) return;
    int xq = idx & 31;
    int y  = (idx >> 5) & (HH - 1);
    int bc = idx >> 12;

    float add = g_osm[(size_t)bc * NN + (y >> 2) * WP + xq];
    size_t off = ((size_t)bc * HH + y) * WW + xq * 4;
    float4 c = *reinterpret_cast<const float4*>(c2 + off);
    c.x += add; c.y += add; c.z += add; c.w += add;
    *reinterpret_cast<float4*>(out + off) = c;
}

// ---------------------------------------------------------------------------
extern "C" void kernel_launch(void* const* d_in, const int* in_sizes, int n_in,
                              void* d_out, int out_size) {
    const float* input = (const float*)d_in[0];
    const float* c2    = (const float*)d_in[1];
    const float* Wq    = (const float*)d_in[2];
    const float* bq    = (const float*)d_in[3];
    const float* Wk    = (const float*)d_in[4];
    const float* bk    = (const float*)d_in[5];
    const float* Wv    = (const float*)d_in[6];
    const float* bv    = (const float*)d_in[7];
    float* out = (float*)d_out;

    bf16 *xT, *yT, *wqb, *wkb, *wvb, *Qp, *Kp, *Vp, *attn;
    float *Ep, *osm;
    cudaGetSymbolAddress((void**)&xT,   g_xT);
    cudaGetSymbolAddress((void**)&yT,   g_yT);
    cudaGetSymbolAddress((void**)&wqb,  g_Wqb);
    cudaGetSymbolAddress((void**)&wkb,  g_Wkb);
    cudaGetSymbolAddress((void**)&wvb,  g_Wvb);
    cudaGetSymbolAddress((void**)&Qp,   g_Q);
    cudaGetSymbolAddress((void**)&Kp,   g_Kt);
    cudaGetSymbolAddress((void**)&Vp,   g_V);
    cudaGetSymbolAddress((void**)&Ep,   g_E);
    cudaGetSymbolAddress((void**)&attn, g_attn);
    cudaGetSymbolAddress((void**)&osm,  g_osm);

    // 1. pool + transpose + bf16 (both tensors);  2. weight conversion
    pool_t_kernel<<<dim3(CC / 32, HP, BB * 2), 1024>>>(input, c2);
    cvt_w_kernel<<<(CC * CC + 255) / 256, 256>>>(Wq, Wk, Wv);

    // 3. Q[n][o] = xT.Wq^T + bq  AND  K[m][o] = yT.Wk^T + bk  (fused, z split)
    mma_tn_kernel<2, true, true><<<dim3(1, 8, 2 * BB), 256>>>(
        xT, wqb, bq, Qp, yT, wkb, bk, Kp,
        CC, CC, CC, CKK, (size_t)NN * CC, 0, (size_t)NN * CKK, BB);

    //    V[c][n] = Wv . yT^T + bv   (M=512, N=1024, K=512), bf16 out
    mma_tn_kernel<1, true, false><<<dim3(8, 4, BB), 256>>>(
        wvb, yT, bv, Vp, nullptr, nullptr, nullptr, nullptr,
        CC, CC, CC, NN, 0, (size_t)NN * CC, (size_t)CC * NN, BB * 64);

    // 4. E[n][m] = Q . K^T          (M=1024, N=1024, K=128), fp32 out
    mma_tn_kernel<0, false, false><<<dim3(8, 8, BB), 256>>>(
        Qp, Kp, nullptr, Ep, nullptr, nullptr, nullptr, nullptr,
        CKK, CKK, CKK, NN, (size_t)NN * CKK, (size_t)NN * CKK, (size_t)NN * NN, BB * 64);

    // 5. softmax rows (scale folded in), bf16 attn out
    softmax_kernel<<<BB * NN, 256>>>();

    // 6. osm[c][n] = V . attn^T     (M=512, N=1024, K=1024), fp32 out
    mma_tn_kernel<0, false, false><<<dim3(8, 4, BB), 256>>>(
        Vp, attn, nullptr, osm, nullptr, nullptr, nullptr, nullptr,
        NN, NN, NN, NN, (size_t)CC * NN, (size_t)NN * NN, (size_t)CC * NN, BB * 64);

    // 7. upsample + residual
    up_add_kernel<<<(BB * CC * HH * (WW / 4) + 255) / 256, 256>>>(c2, out);
}

// round 6
// speedup vs baseline: 4.5060x; 1.0407x over previous
#include <cuda_runtime.h>
#include <cuda_bf16.h>
#include <stdint.h>

#define BB   8
#define CC   512
#define HH   128
#define WW   128
#define HP   32
#define WP   32
#define NN   1024        // HP*WP tokens
#define CKK  128         // C/4

typedef __nv_bfloat16 bf16;

// ------------------------- scratch (static device globals) -------------------
__device__ bf16  g_xT[(size_t)BB * NN * CC];     // pooled input, [b][n][c]
__device__ bf16  g_yT[(size_t)BB * NN * CC];     // pooled c2,    [b][n][c]
__device__ bf16  g_Wqb[CKK * CC];
__device__ bf16  g_Wkb[CKK * CC];
__device__ bf16  g_Wvb[CC * CC];
__device__ bf16  g_Q [(size_t)BB * NN * CKK];    // [b][n][o]
__device__ bf16  g_Kt[(size_t)BB * NN * CKK];    // [b][m][o]
__device__ bf16  g_V [(size_t)BB * CC * NN];     // [b][c][n]
__device__ float g_E [(size_t)BB * NN * NN];     // [b][n][m]
__device__ bf16  g_attn[(size_t)BB * NN * NN];   // [b][n][m] softmaxed
__device__ float g_osm[(size_t)BB * CC * NN];    // [b][c][n] attention out

// ---------------------------------------------------------------------------
// Kernel 1: fused 4x4 avg-pool + transpose + bf16 convert (both tensors).
// ---------------------------------------------------------------------------
__global__ __launch_bounds__(1024) void pool_t_kernel(const float* __restrict__ in,
                                                      const float* __restrict__ c2) {
    const int cg = blockIdx.x;
    const int ph = blockIdx.y;
    const int b  = blockIdx.z >> 1;
    const float* __restrict__ src = (blockIdx.z & 1) ? c2 : in;
    bf16* __restrict__ dst            = (blockIdx.z & 1) ? g_yT : g_xT;

    const int t  = threadIdx.x;
    const int cl = t >> 5;
    const int pw = t & 31;

    const size_t base = ((size_t)(b * CC + cg * 32 + cl) * HH + ph * 4) * WW + pw * 4;
    float s = 0.f;
#pragma unroll
    for (int r = 0; r < 4; r++) {
        float4 v = *reinterpret_cast<const float4*>(src + base + r * WW);
        s += v.x + v.y + v.z + v.w;
    }

    __shared__ bf16 tile[32][33];
    tile[pw][cl] = __float2bfloat16(s * (1.f / 16.f));
    __syncthreads();

    const int pwo = t >> 5, clo = t & 31;
    dst[((size_t)b * NN + ph * 32 + pwo) * CC + cg * 32 + clo] = tile[pwo][clo];
}

// ---------------------------------------------------------------------------
// Kernel 2: fp32 -> bf16 weight conversion
// ---------------------------------------------------------------------------
__global__ __launch_bounds__(256) void cvt_w_kernel(const float* __restrict__ Wq,
                                                    const float* __restrict__ Wk,
                                                    const float* __restrict__ Wv) {
    int i = blockIdx.x * 256 + threadIdx.x;
    if (i < CKK * CC) {
        g_Wqb[i] = __float2bfloat16(Wq[i]);
        g_Wkb[i] = __float2bfloat16(Wk[i]);
    }
    if (i < CC * CC) g_Wvb[i] = __float2bfloat16(Wv[i]);
}

// ---------------------------------------------------------------------------
// PTX helpers
// ---------------------------------------------------------------------------
__device__ __forceinline__ void mma_bf16(float* c, const uint32_t* a, const uint32_t* b) {
    asm volatile(
        "mma.sync.aligned.m16n8k16.row.col.f32.bf16.bf16.f32 "
        "{%0,%1,%2,%3}, {%4,%5,%6,%7}, {%8,%9}, {%0,%1,%2,%3};"
        : "+f"(c[0]), "+f"(c[1]), "+f"(c[2]), "+f"(c[3])
        : "r"(a[0]), "r"(a[1]), "r"(a[2]), "r"(a[3]), "r"(b[0]), "r"(b[1]));
}

__device__ __forceinline__ void cp16(uint32_t saddr, const void* gptr) {
    asm volatile("cp.async.cg.shared.global [%0], [%1], 16;" :: "r"(saddr), "l"(gptr));
}
__device__ __forceinline__ void cp_commit() { asm volatile("cp.async.commit_group;"); }
__device__ __forceinline__ void cp_wait1()  { asm volatile("cp.async.wait_group 1;"); }

__device__ __forceinline__ void ldsm_x4(uint32_t* r, uint32_t saddr) {
    asm volatile("ldmatrix.sync.aligned.m8n8.x4.shared.b16 {%0,%1,%2,%3}, [%4];"
        : "=r"(r[0]), "=r"(r[1]), "=r"(r[2]), "=r"(r[3]) : "r"(saddr));
}

// ---------------------------------------------------------------------------
// GEMM core: TN bf16 mma.sync, 3-stage cp.async ring, ldmatrix frags.
//   C[m][n] = sum_k A[m][k] * B[n][k]  (+bias)
// Block tile 128x128, BK=32, 8 warps (2x2x4), warp tile 64x32.
// biasMode: 0 none, 1 per-row(m), 2 per-col(n) (runtime; epilogue only).
// All dims exact multiples -> no guards.
// ---------------------------------------------------------------------------
#define SAS 40          // smem row stride (bf16): ldmatrix rows hit 8 distinct 16B groups
#define STG 3           // pipeline stages
#define STAGE_B (128 * SAS * 2)              // bytes per operand stage
#define SMEM_BYTES (STG * STAGE_B * 2)       // both operands

template <bool OUT_BF16>
__device__ __forceinline__ void gemm_core(
    const bf16* __restrict__ Ab, const bf16* __restrict__ Bb,
    const float* __restrict__ bias, void* __restrict__ Cb,
    int Kk, int lda, int ldb, int ldc, int biasMode,
    int m0, int n0, bf16* sMem) {

    const int t    = threadIdx.x;
    const int warp = t >> 5;
    const int lane = t & 31;
    const int wm   = (warp >> 2) * 64;
    const int wn   = (warp & 3) * 32;
    const int g    = lane >> 2;
    const int tg   = lane & 3;

    const int ldr = t >> 2;               // 0..63 base row
    const int ldo = (t & 3) * 8;          // k offset in elements

    const uint32_t sAb = (uint32_t)__cvta_generic_to_shared(sMem);
    const uint32_t sBb = sAb + STG * STAGE_B;

    // ldmatrix per-lane offsets
    const int aRow = (lane & 7) + ((lane >> 3) & 1) * 8;
    const int aKof = (lane >> 4) * 8;
    const int bRow = (lane & 7) + ((lane >> 4) & 1) * 8;
    const int bKof = ((lane >> 3) & 1) * 8;

    float acc[4][4][4];
#pragma unroll
    for (int i = 0; i < 4; i++)
#pragma unroll
        for (int j = 0; j < 4; j++)
#pragma unroll
            for (int e = 0; e < 4; e++) acc[i][j][e] = 0.f;

    const int KT = Kk >> 5;

    auto load_tile = [&](int kt, int s) {
        uint32_t sa = sAb + s * STAGE_B;
        uint32_t sb = sBb + s * STAGE_B;
        int k0 = kt * 32;
#pragma unroll
        for (int i = 0; i < 2; i++) {
            int r = ldr + 64 * i;
            cp16(sa + (r * SAS + ldo) * 2, &Ab[(size_t)(m0 + r) * lda + k0 + ldo]);
            cp16(sb + (r * SAS + ldo) * 2, &Bb[(size_t)(n0 + r) * ldb + k0 + ldo]);
        }
    };

    load_tile(0, 0); cp_commit();
    load_tile(1, 1); cp_commit();

    int s_comp = 0, s_load = 2;
    for (int kt = 0; kt < KT; kt++) {
        cp_wait1();                    // oldest outstanding group (tile kt) complete
        __syncthreads();               // all warps past compute on the slot we refill
        if (kt + 2 < KT) {
            load_tile(kt + 2, s_load);
            if (++s_load == STG) s_load = 0;
        }
        cp_commit();                   // empty group at tail keeps wait semantics exact

        uint32_t saS = sAb + s_comp * STAGE_B;
        uint32_t sbS = sBb + s_comp * STAGE_B;
#pragma unroll
        for (int ks = 0; ks < 32; ks += 16) {
            uint32_t afr[4][4];
#pragma unroll
            for (int mi = 0; mi < 4; mi++) {
                int row = wm + mi * 16 + aRow;
                ldsm_x4(afr[mi], saS + (row * SAS + ks + aKof) * 2);
            }
            uint32_t bfr[4][2];
#pragma unroll
            for (int nj2 = 0; nj2 < 2; nj2++) {
                uint32_t btmp[4];
                int col = wn + nj2 * 16 + bRow;
                ldsm_x4(btmp, sbS + (col * SAS + ks + bKof) * 2);
                bfr[nj2 * 2][0]     = btmp[0];
                bfr[nj2 * 2][1]     = btmp[1];
                bfr[nj2 * 2 + 1][0] = btmp[2];
                bfr[nj2 * 2 + 1][1] = btmp[3];
            }
#pragma unroll
            for (int mi = 0; mi < 4; mi++)
#pragma unroll
                for (int nj = 0; nj < 4; nj++)
                    mma_bf16(acc[mi][nj], afr[mi], bfr[nj]);
        }
        if (++s_comp == STG) s_comp = 0;
    }

    // epilogue
#pragma unroll
    for (int mi = 0; mi < 4; mi++) {
#pragma unroll
        for (int nj = 0; nj < 4; nj++) {
            int row = m0 + wm + mi * 16 + g;
            int col = n0 + wn + nj * 8 + 2 * tg;
            float c0 = acc[mi][nj][0], c1 = acc[mi][nj][1];
            float c2v = acc[mi][nj][2], c3v = acc[mi][nj][3];
            if (biasMode == 1) {
                float br0 = bias[row], br1 = bias[row + 8];
                c0 += br0; c1 += br0; c2v += br1; c3v += br1;
            } else if (biasMode == 2) {
                float bc0 = bias[col], bc1 = bias[col + 1];
                c0 += bc0; c1 += bc1; c2v += bc0; c3v += bc1;
            }
            if (OUT_BF16) {
                bf16* Co = reinterpret_cast<bf16*>(Cb);
                __nv_bfloat162 p0 = __floats2bfloat162_rn(c0, c1);
                __nv_bfloat162 p1 = __floats2bfloat162_rn(c2v, c3v);
                *reinterpret_cast<__nv_bfloat162*>(&Co[(size_t)row * ldc + col]) = p0;
                *reinterpret_cast<__nv_bfloat162*>(&Co[(size_t)(row + 8) * ldc + col]) = p1;
            } else {
                float* Cf = reinterpret_cast<float*>(Cb);
                *reinterpret_cast<float2*>(&Cf[(size_t)row * ldc + col]) = make_float2(c0, c1);
                *reinterpret_cast<float2*>(&Cf[(size_t)(row + 8) * ldc + col]) = make_float2(c2v, c3v);
            }
        }
    }
}

// ---------------------------------------------------------------------------
// Kernel 3a: fused Q + K + V projections, one flat 384-block launch.
//   blocks [0,128):  Q/K  — C[n][o] = pooled . W^T + b   (z<8 -> Q, else K)
//   blocks [128,384): V   — C[c][n] = Wv . pooled^T + bv
// ---------------------------------------------------------------------------
__global__ __launch_bounds__(256, 2) void qkv_kernel() {
    extern __shared__ bf16 sMem[];
    int fb = blockIdx.x;

    const bf16 *A, *B;
    const float* bias;
    bf16* C;
    int m0, n0, biasMode, ldc;

    if (fb < 128) {
        int z  = fb >> 3;
        m0 = (fb & 7) * 128; n0 = 0; biasMode = 2; ldc = CKK;
        if (z < 8) {
            A = g_xT + (size_t)z * NN * CC; B = g_Wqb;
            bias = nullptr; C = g_Q + (size_t)z * NN * CKK;
            biasMode = 2;
        } else {
            z -= 8;
            A = g_yT + (size_t)z * NN * CC; B = g_Wkb;
            C = g_Kt + (size_t)z * NN * CKK;
        }
        // bias pointer resolved below (needs device-symbol passing); use params instead
    } else {
        int f2 = fb - 128;
        int z  = f2 >> 5, rem = f2 & 31;
        m0 = (rem >> 3) * 128; n0 = (rem & 7) * 128; biasMode = 1; ldc = NN;
        A = g_Wvb; B = g_yT + (size_t)z * NN * CC;
        C = g_V + (size_t)z * CC * NN;
    }
    (void)bias;
    // bias arrays passed via constant params:
    // (declared below as kernel parameters in wrapper)
    return; // placeholder (real kernel below)
}

// Real fused kernel with bias params.
__global__ __launch_bounds__(256, 2) void qkv_fused_kernel(
    const float* __restrict__ bq, const float* __restrict__ bk,
    const float* __restrict__ bv) {
    extern __shared__ bf16 sMem[];
    int fb = blockIdx.x;

    const bf16 *A, *B;
    const float* bias;
    bf16* C;
    int m0, n0, biasMode, ldc;

    if (fb < 128) {
        int z  = fb >> 3;
        m0 = (fb & 7) * 128; n0 = 0; biasMode = 2; ldc = CKK;
        if (z < 8) {
            A = g_xT + (size_t)z * NN * CC; B = g_Wqb; bias = bq;
            C = g_Q + (size_t)z * NN * CKK;
        } else {
            z -= 8;
            A = g_yT + (size_t)z * NN * CC; B = g_Wkb; bias = bk;
            C = g_Kt + (size_t)z * NN * CKK;
        }
    } else {
        int f2 = fb - 128;
        int z  = f2 >> 5, rem = f2 & 31;
        m0 = (rem >> 3) * 128; n0 = (rem & 7) * 128; biasMode = 1; ldc = NN;
        A = g_Wvb; B = g_yT + (size_t)z * NN * CC; bias = bv;
        C = g_V + (size_t)z * CC * NN;
    }
    gemm_core<true>(A, B, bias, C, CC, CC, CC, ldc, biasMode, m0, n0, sMem);
}

// ---------------------------------------------------------------------------
// Kernel 3b: generic batched TN GEMM, fp32 out, no bias (E and AV).
// ---------------------------------------------------------------------------
__global__ __launch_bounds__(256, 2) void gemm_f32_kernel(
    const bf16* __restrict__ A, const bf16* __restrict__ B, float* __restrict__ C,
    int Kk, int lda, int ldb, int ldc,
    size_t strA, size_t strB, size_t strC) {
    extern __shared__ bf16 sMem[];
    gemm_core<false>(A + strA * blockIdx.z, B + strB * blockIdx.z, nullptr,
                     C + strC * blockIdx.z, Kk, lda, ldb, ldc, 0,
                     blockIdx.y * 128, blockIdx.x * 128, sMem);
}

// ---------------------------------------------------------------------------
// Kernel 4: row softmax of scale*E (N=1024), fp32 in -> bf16 out.
// ---------------------------------------------------------------------------
__global__ __launch_bounds__(256) void softmax_kernel() {
    __shared__ float red[8];
    const float* __restrict__ p = g_E + (size_t)blockIdx.x * NN;
    bf16* __restrict__ po       = g_attn + (size_t)blockIdx.x * NN;
    const int t = threadIdx.x;
    const float scale = 0.088388347648318447f;   // 128^-0.5

    float v[4];
    float mx = -3.4e38f;
#pragma unroll
    for (int i = 0; i < 4; i++) {
        v[i] = p[t + 256 * i] * scale;
        mx = fmaxf(mx, v[i]);
    }
#pragma unroll
    for (int o = 16; o > 0; o >>= 1) mx = fmaxf(mx, __shfl_xor_sync(0xffffffffu, mx, o));
    if ((t & 31) == 0) red[t >> 5] = mx;
    __syncthreads();
    if (t < 8) {
        float m = red[t];
#pragma unroll
        for (int o = 4; o > 0; o >>= 1) m = fmaxf(m, __shfl_xor_sync(0xffu, m, o));
        red[t] = m;
    }
    __syncthreads();
    mx = red[0];

    float s = 0.f;
#pragma unroll
    for (int i = 0; i < 4; i++) {
        v[i] = __expf(v[i] - mx);
        s += v[i];
    }
#pragma unroll
    for (int o = 16; o > 0; o >>= 1) s += __shfl_xor_sync(0xffffffffu, s, o);
    __syncthreads();
    if ((t & 31) == 0) red[t >> 5] = s;
    __syncthreads();
    if (t < 8) {
        float m = red[t];
#pragma unroll
        for (int o = 4; o > 0; o >>= 1) m += __shfl_xor_sync(0xffu, m, o);
        red[t] = m;
    }
    __syncthreads();
    float inv = 1.f / red[0];
#pragma unroll
    for (int i = 0; i < 4; i++) po[t + 256 * i] = __float2bfloat16(v[i] * inv);
}

// ---------------------------------------------------------------------------
// Kernel 5: nearest upsample 4x + residual add.
// ---------------------------------------------------------------------------
__global__ __launch_bounds__(256) void up_add_kernel(const float* __restrict__ c2,
                                                     float* __restrict__ out) {
    int idx = blockIdx.x * 256 + threadIdx.x;
    if (idx >= BB * CC * HH * (WW / 4)) return;
    int xq = idx & 31;
    int y  = (idx >> 5) & (HH - 1);
    int bc = idx >> 12;

    float add = g_osm[(size_t)bc * NN + (y >> 2) * WP + xq];
    size_t off = ((size_t)bc * HH + y) * WW + xq * 4;
    float4 c = *reinterpret_cast<const float4*>(c2 + off);
    c.x += add; c.y += add; c.z += add; c.w += add;
    *reinterpret_cast<float4*>(out + off) = c;
}

// ---------------------------------------------------------------------------
extern "C" void kernel_launch(void* const* d_in, const int* in_sizes, int n_in,
                              void* d_out, int out_size) {
    const float* input = (const float*)d_in[0];
    const float* c2    = (const float*)d_in[1];
    const float* Wq    = (const float*)d_in[2];
    const float* bq    = (const float*)d_in[3];
    const float* Wk    = (const float*)d_in[4];
    const float* bk    = (const float*)d_in[5];
    const float* Wv    = (const float*)d_in[6];
    const float* bv    = (const float*)d_in[7];
    float* out = (float*)d_out;

    bf16 *Qp, *Kp, *Vp, *attn;
    float *Ep, *osm;
    cudaGetSymbolAddress((void**)&Qp,   g_Q);
    cudaGetSymbolAddress((void**)&Kp,   g_Kt);
    cudaGetSymbolAddress((void**)&Vp,   g_V);
    cudaGetSymbolAddress((void**)&Ep,   g_E);
    cudaGetSymbolAddress((void**)&attn, g_attn);
    cudaGetSymbolAddress((void**)&osm,  g_osm);

    cudaFuncSetAttribute(qkv_fused_kernel,
                         cudaFuncAttributeMaxDynamicSharedMemorySize, SMEM_BYTES);
    cudaFuncSetAttribute(gemm_f32_kernel,
                         cudaFuncAttributeMaxDynamicSharedMemorySize, SMEM_BYTES);

    // 1. pool + transpose + bf16 (both tensors);  2. weight conversion
    pool_t_kernel<<<dim3(CC / 32, HP, BB * 2), 1024>>>(input, c2);
    cvt_w_kernel<<<(CC * CC + 255) / 256, 256>>>(Wq, Wk, Wv);

    // 3. fused Q + K + V projections (384 blocks, fills the chip)
    qkv_fused_kernel<<<384, 256, SMEM_BYTES>>>(bq, bk, bv);

    // 4. E[n][m] = Q . K^T          (M=1024, N=1024, K=128), fp32 out
    gemm_f32_kernel<<<dim3(8, 8, BB), 256, SMEM_BYTES>>>(
        Qp, Kp, Ep, CKK, CKK, CKK, NN,
        (size_t)NN * CKK, (size_t)NN * CKK, (size_t)NN * NN);

    // 5. softmax rows (scale folded in), bf16 attn out
    softmax_kernel<<<BB * NN, 256>>>();

    // 6. osm[c][n] = V . attn^T     (M=512, N=1024, K=1024), fp32 out
    gemm_f32_kernel<<<dim3(8, 4, BB), 256, SMEM_BYTES>>>(
        Vp, attn, osm, NN, NN, NN, NN,
        (size_t)CC * NN, (size_t)NN * NN, (size_t)CC * NN);

    // 7. upsample + residual
    up_add_kernel<<<(BB * CC * HH * (WW / 4) + 255) / 256, 256>>>(c2, out);
}